// round 17
// baseline (speedup 1.0000x reference)
#include <cuda_runtime.h>
#include <cuda_fp16.h>
#include <cstdint>

// Problem constants (fixed by the dataset):
//   N = 50000 nodes, C = 128 channels, E = 400000 edges,
//   T = 12 edge types, P = 16 (4x4 restriction map)
// Y layout per node: [half(src=0/dst=1)][t][p]  -> 2*12*16 = 384 cols
#define NMAX   50000
#define CDIM   128
#define NCOLS  384

// Scratch (allocation-free rule: __device__ globals)
__device__ __half g_Yh[(size_t)NMAX * NCOLS];        // 38.4 MB, fp16 node partials

__device__ __forceinline__ uint32_t smem_u32(const void* p) {
    return (uint32_t)__cvta_generic_to_shared(p);
}
__device__ __forceinline__ void ldsm_x4(uint32_t& r0, uint32_t& r1,
                                        uint32_t& r2, uint32_t& r3,
                                        uint32_t addr) {
    asm volatile("ldmatrix.sync.aligned.m8n8.x4.shared.b16 {%0,%1,%2,%3}, [%4];"
                 : "=r"(r0), "=r"(r1), "=r"(r2), "=r"(r3) : "r"(addr));
}
__device__ __forceinline__ void ldsm_x4_trans(uint32_t& r0, uint32_t& r1,
                                              uint32_t& r2, uint32_t& r3,
                                              uint32_t addr) {
    asm volatile("ldmatrix.sync.aligned.m8n8.x4.trans.shared.b16 {%0,%1,%2,%3}, [%4];"
                 : "=r"(r0), "=r"(r1), "=r"(r2), "=r"(r3) : "r"(addr));
}
__device__ __forceinline__ float fast_tanh(float x) {
    float y;
    asm("tanh.approx.f32 %0, %1;" : "=f"(y) : "f"(x));
    return y;
}

// ---------------------------------------------------------------------------
// Kernel 1: Y[M,384] = fp16(X[M,128]) @ B^T, fp32 acc, fp16 out — with B
// loaded DIRECTLY from W (no prep kernel). For n-block nb, the 128 n-values
// map to 8 W blocks g = nb*8+b (g = half*12 + t), each a [128 k][16 p]
// f32 matrix at W + (t*256 + half*128)*16. Each CTA LDGs them coalesced
// (L2-resident), cvts to fp16, stores to smem in natural [k][n] (MN-major)
// layout, and feeds mma's B operand via ldmatrix.x4.TRANS.
//
// Grid (ceil(M/128), 1): A tile loaded ONCE, 3 n-blocks looped in-CTA.
// 8 warps in 4(M) x 2(N); warp tile 32x64, mma.m16n8k16.f16 (fp32 acc).
// As rows: SPAD=136 halves -> conflict-free A LDSM phases (as R14/R16).
// Bs rows: 136 halves (272 B): trans-LDSM 8 k-rows hit bank groups 4r ->
// all 32 banks once -> conflict-free.
// ---------------------------------------------------------------------------
#define SPAD      136
#define AS_ELEMS  (128 * SPAD)
#define GEMM_SMEM_BYTES (2 * AS_ELEMS * 2)   // 69632 B (dynamic, opt-in)

__global__ void __launch_bounds__(256, 2)
gemm_kernel(const float* __restrict__ X, const float* __restrict__ W, int M) {
    extern __shared__ __half smem[];
    __half* As = smem;              // [128 m][SPAD]   cols = k
    __half* Bs = smem + AS_ELEMS;   // [128 k][SPAD]   cols = n_local

    const int m0  = blockIdx.x * 128;
    const int tid = threadIdx.x;

    // ---- A tile (once): LDG f32x4 -> cvt fp16 -> STS 8 B ----
    #pragma unroll
    for (int i = 0; i < 16; ++i) {
        int li = tid + i * 256;          // 0..4095
        int r  = li >> 5;                // m row 0..127
        int c  = (li & 31) << 2;         // k col (f32 granularity)
        float4 v = make_float4(0.f, 0.f, 0.f, 0.f);
        if (m0 + r < M)
            v = *reinterpret_cast<const float4*>(X + (size_t)(m0 + r) * CDIM + c);
        __half2 h0 = __floats2half2_rn(v.x, v.y);
        __half2 h1 = __floats2half2_rn(v.z, v.w);
        *reinterpret_cast<__half2*>(As + r * SPAD + c)     = h0;
        *reinterpret_cast<__half2*>(As + r * SPAD + c + 2) = h1;
    }

    const int warp = tid >> 5;
    const int lane = tid & 31;
    const int wm   = warp >> 1;   // 0..3
    const int wn   = warp & 1;    // 0..1
    const int mat  = lane >> 3;
    const int mrl  = lane & 7;

    // A fragment addresses (k-major, normal ldmatrix), advance 32 B per k16.
    uint32_t a_addr[2];
    #pragma unroll
    for (int mt = 0; mt < 2; ++mt) {
        int row = wm * 32 + mt * 16 + (mat & 1) * 8 + mrl;
        int col = (mat >> 1) * 8;
        a_addr[mt] = smem_u32(As + row * SPAD + col);
    }
    // B fragment addresses (MN-major [k][n], TRANS ldmatrix).
    // Group g covers nt=2g (mats 0,1 = k0,k8) and nt=2g+1 (mats 2,3).
    // Advance 16 k-rows = 16*SPAD*2 bytes per k16 step.
    uint32_t b_addr[4];
    #pragma unroll
    for (int g = 0; g < 4; ++g) {
        int krow = (mat & 1) * 8 + mrl;
        int col  = wn * 64 + (2 * g + (mat >> 1)) * 8;
        b_addr[g] = smem_u32(Bs + krow * SPAD + col);
    }

    const int grp   = lane >> 2;
    const int tig   = lane & 3;
    const int rbase = wm * 32 + grp;

    // ---- Loop over the 3 n-blocks, reusing A and acc registers ----
    for (int nb = 0; nb < 3; ++nb) {
        const int n0 = nb * 128;

        // B tile from W: 8 blocks x 2048 f32, coalesced float4 (16/thread),
        // cvt fp16, STS 8 B into [k][n_local] rows.
        #pragma unroll
        for (int i = 0; i < 16; ++i) {
            int li  = tid + i * 256;          // 0..4095
            int j   = li << 2;                // float offset in 16K-float slab
            int b   = j >> 11;                // W block 0..7
            int rem = j & 2047;               // k*16 + p
            int k   = rem >> 4;
            int p   = rem & 15;               // multiple of 4
            int g   = nb * 8 + b;
            int hf  = (g >= 12);
            int t   = g - hf * 12;
            float4 v = *reinterpret_cast<const float4*>(
                W + (((size_t)(t * 256 + hf * 128)) << 4) + rem);
            __half2 h0 = __floats2half2_rn(v.x, v.y);
            __half2 h1 = __floats2half2_rn(v.z, v.w);
            __half* dst = Bs + k * SPAD + b * 16 + p;
            *reinterpret_cast<__half2*>(dst)     = h0;
            *reinterpret_cast<__half2*>(dst + 2) = h1;
        }
        __syncthreads();                      // B (and, on nb=0, A) visible

        float acc[2][8][4];
        #pragma unroll
        for (int mt = 0; mt < 2; ++mt)
            #pragma unroll
            for (int nt = 0; nt < 8; ++nt)
                #pragma unroll
                for (int q = 0; q < 4; ++q)
                    acc[mt][nt][q] = 0.f;

        #pragma unroll
        for (int ks = 0; ks < CDIM / 16; ++ks) {      // 8 k16 steps
            const uint32_t akoff = ks * 32;           // A: 16 halves = 32 B
            const uint32_t bkoff = ks * (16 * SPAD * 2);  // B: 16 k-rows
            uint32_t a[2][4];
            #pragma unroll
            for (int mt = 0; mt < 2; ++mt)
                ldsm_x4(a[mt][0], a[mt][1], a[mt][2], a[mt][3],
                        a_addr[mt] + akoff);
            uint32_t b[8][2];
            #pragma unroll
            for (int g = 0; g < 4; ++g)
                ldsm_x4_trans(b[2 * g][0], b[2 * g][1],
                              b[2 * g + 1][0], b[2 * g + 1][1],
                              b_addr[g] + bkoff);
            #pragma unroll
            for (int nt = 0; nt < 8; ++nt) {
                #pragma unroll
                for (int mt = 0; mt < 2; ++mt) {
                    asm volatile(
                        "mma.sync.aligned.m16n8k16.row.col.f32.f16.f16.f32 "
                        "{%0,%1,%2,%3}, {%4,%5,%6,%7}, {%8,%9}, {%0,%1,%2,%3};"
                        : "+f"(acc[mt][nt][0]), "+f"(acc[mt][nt][1]),
                          "+f"(acc[mt][nt][2]), "+f"(acc[mt][nt][3])
                        : "r"(a[mt][0]), "r"(a[mt][1]),
                          "r"(a[mt][2]), "r"(a[mt][3]),
                          "r"(b[nt][0]), "r"(b[nt][1]));
                }
            }
        }

        // Epilogue for this n-block: fp16 half2 stores
        #pragma unroll
        for (int mt = 0; mt < 2; ++mt) {
            int r0 = m0 + rbase + mt * 16;
            #pragma unroll
            for (int nt = 0; nt < 8; ++nt) {
                int cc = n0 + wn * 64 + nt * 8 + tig * 2;
                if (r0 < M) {
                    __half2 h = __floats2half2_rn(acc[mt][nt][0], acc[mt][nt][1]);
                    *reinterpret_cast<__half2*>(g_Yh + (size_t)r0 * NCOLS + cc) = h;
                }
                if (r0 + 8 < M) {
                    __half2 h = __floats2half2_rn(acc[mt][nt][2], acc[mt][nt][3]);
                    *reinterpret_cast<__half2*>(g_Yh + (size_t)(r0 + 8) * NCOLS + cc) = h;
                }
            }
        }
        __syncthreads();   // all warps done reading Bs before next overwrite
    }
}

// ---------------------------------------------------------------------------
// Kernel 2: TWO threads per edge (measured-best gather shape).
// Each thread: 3 index loads + 2 independent 16 B gathers + 8 MUFU tanh +
// 32 B coalesced output. Index-dtype detect fused per block (edge_types in
// 0..11: if int64 LE, every odd int32 word is 0; FP prob (1/12)^256).
// ---------------------------------------------------------------------------
__global__ void edge_kernel(const void* __restrict__ ei,
                            const void* __restrict__ et,
                            float* __restrict__ out, int E) {
    const int* etw = (const int*)et;
    int probe = etw[2 * threadIdx.x + 1];
    int idx64 = !__syncthreads_or(probe != 0);

    int gid = blockIdx.x * blockDim.x + threadIdx.x;
    int e = gid >> 1;
    if (e >= E) return;
    int h = (gid & 1) << 3;   // 0 or 8 (element offset within the 16)

    int src, dst, t;
    if (idx64) {
        const long long* ei64 = (const long long*)ei;
        const long long* et64 = (const long long*)et;
        src = (int)ei64[e];
        dst = (int)ei64[(size_t)E + e];
        t   = (int)et64[e];
    } else {
        const int* ei32 = (const int*)ei;
        src = ei32[e];
        dst = ei32[(size_t)E + e];
        t   = etw[e];
    }

    const uint4 va = *reinterpret_cast<const uint4*>(
        g_Yh + (size_t)src * NCOLS + t * 16 + h);
    const uint4 vb = *reinterpret_cast<const uint4*>(
        g_Yh + (size_t)dst * NCOLS + 192 + t * 16 + h);
    const __half2* pa = reinterpret_cast<const __half2*>(&va);
    const __half2* pb = reinterpret_cast<const __half2*>(&vb);

    float r[8];
    #pragma unroll
    for (int i = 0; i < 4; ++i) {
        float2 fa = __half22float2(pa[i]);
        float2 fb = __half22float2(pb[i]);
        r[2 * i]     = fast_tanh(fa.x + fb.x);
        r[2 * i + 1] = fast_tanh(fa.y + fb.y);
    }
    float* o = out + (size_t)e * 16 + h;
    *reinterpret_cast<float4*>(o)     = make_float4(r[0], r[1], r[2], r[3]);
    *reinterpret_cast<float4*>(o + 4) = make_float4(r[4], r[5], r[6], r[7]);
}

// ---------------------------------------------------------------------------
extern "C" void kernel_launch(void* const* d_in, const int* in_sizes, int n_in,
                              void* d_out, int out_size) {
    const float* x  = (const float*)d_in[0];      // [N,128] f32
    const void*  ei = d_in[1];                    // [2,E] int32 or int64
    const void*  et = d_in[2];                    // [E]   int32 or int64
    const float* W  = (const float*)d_in[3];      // [12,256,16] f32

    const int N = in_sizes[0] / CDIM;
    const int E = in_sizes[2];

    // Opt-in >48 KB dynamic smem (immediate host attr set; capture-legal,
    // unconditional -> deterministic).
    cudaFuncSetAttribute(gemm_kernel,
                         cudaFuncAttributeMaxDynamicSharedMemorySize,
                         GEMM_SMEM_BYTES);

    // 1) Dense node-side GEMM, B loaded directly from W (no prep kernel)
    dim3 grid((N + 127) / 128, 1);
    gemm_kernel<<<grid, 256, GEMM_SMEM_BYTES>>>(x, W, N);

    // 2) Edge gather + add + tanh, 2 threads/edge
    int threads = E * 2;
    edge_kernel<<<(threads + 255) / 256, 256>>>(ei, et, (float*)d_out, E);
}